// round 2
// baseline (speedup 1.0000x reference)
#include <cuda_runtime.h>
#include <cuda_bf16.h>
#include <cstdint>

// PSAvgPooling: B=8, H=64, W=64, C=1152, N=512 boxes/image
// NUM_BINS=3 (TB=9), CROP=3, Cs = C/TB = 128.
//
// out[box, c] = (1/81) * sum_bin w[bin] * sum_{3x3 samples} bilinear(img[.,., bin*128+c])
//
// Layout: one warp per box; each lane owns 4 channels (float4).
// Every gather is one LDG.128; 32 lanes cover the 512B channel slice.
// Bin loops NOT unrolled (I$ footprint); 3x3 sample loop fully unrolled
// (36 independent LDG.128 in flight per bin — saturates per-warp MLP).

#define IMG_H 64
#define IMG_W 64
#define IMG_C 1152
#define CS    128           // channels per bin slice
#define NBINS 3
#define TBINS 9
#define CROP  3
#define BOXES_PER_BLOCK 4   // 4 warps / block

__global__ __launch_bounds__(32 * BOXES_PER_BLOCK)
void ps_pool_kernel(const float* __restrict__ img,
                    const float* __restrict__ boxes,
                    const float* __restrict__ wts,
                    float* __restrict__ out,
                    int boxes_per_image,
                    int total_boxes)
{
    const int warp = threadIdx.x >> 5;
    const int lane = threadIdx.x & 31;
    const int box  = blockIdx.x * BOXES_PER_BLOCK + warp;
    if (box >= total_boxes) return;

    const int b_img = box / boxes_per_image;
    const float* __restrict__ im =
        img + (size_t)b_img * (IMG_H * (size_t)IMG_W * IMG_C);

    // box coords (broadcast load — all lanes same address)
    const float y1 = __ldg(&boxes[box * 4 + 0]);
    const float x1 = __ldg(&boxes[box * 4 + 1]);
    const float y2 = __ldg(&boxes[box * 4 + 2]);
    const float x2 = __ldg(&boxes[box * 4 + 3]);
    const float sy = (y2 - y1) * (1.0f / NBINS);
    const float sx = (x2 - x1) * (1.0f / NBINS);

    float4 acc = make_float4(0.f, 0.f, 0.f, 0.f);

    #pragma unroll 1
    for (int by = 0; by < NBINS; by++) {
        // 3 y-sample rows for this bin row (shared across bx)
        int   y0i[CROP], y1i[CROP];
        float wyv[CROP];
        bool  iny[CROP];
        #pragma unroll
        for (int py = 0; py < CROP; py++) {
            float yy = (y1 + ((float)by + 0.5f * (float)py) * sy) * (float)(IMG_H - 1);
            iny[py] = (yy >= 0.f) && (yy <= (float)(IMG_H - 1));
            float y0f = floorf(yy);
            wyv[py] = yy - y0f;
            int y0 = (int)y0f;
            y0 = min(max(y0, 0), IMG_H - 1);
            y0i[py] = y0;
            y1i[py] = min(y0 + 1, IMG_H - 1);
        }

        #pragma unroll 1
        for (int bx = 0; bx < NBINS; bx++) {
            const int bin = by * NBINS + bx;
            const float* __restrict__ base = im + bin * CS + lane * 4;
            const float wb = __ldg(&wts[bin]);

            // 3 x-sample columns for this bin
            int   x0i[CROP], x1i[CROP];
            float wxv[CROP];
            bool  inx[CROP];
            #pragma unroll
            for (int px = 0; px < CROP; px++) {
                float xx = (x1 + ((float)bx + 0.5f * (float)px) * sx) * (float)(IMG_W - 1);
                inx[px] = (xx >= 0.f) && (xx <= (float)(IMG_W - 1));
                float x0f = floorf(xx);
                wxv[px] = xx - x0f;
                int x0 = (int)x0f;
                x0 = min(max(x0, 0), IMG_W - 1);
                x0i[px] = x0;
                x1i[px] = min(x0 + 1, IMG_W - 1);
            }

            float4 bsum = make_float4(0.f, 0.f, 0.f, 0.f);

            #pragma unroll
            for (int py = 0; py < CROP; py++) {
                const float wy  = wyv[py];
                const size_t r0 = (size_t)y0i[py] * IMG_W;
                const size_t r1 = (size_t)y1i[py] * IMG_W;
                #pragma unroll
                for (int px = 0; px < CROP; px++) {
                    const float wx = wxv[px];
                    const float m  = (iny[py] && inx[px]) ? 1.0f : 0.0f;
                    const float w00 = m * (1.f - wy) * (1.f - wx);
                    const float w01 = m * (1.f - wy) * wx;
                    const float w10 = m * wy * (1.f - wx);
                    const float w11 = m * wy * wx;

                    const float4 v00 = *(const float4*)(base + (r0 + x0i[px]) * IMG_C);
                    const float4 v01 = *(const float4*)(base + (r0 + x1i[px]) * IMG_C);
                    const float4 v10 = *(const float4*)(base + (r1 + x0i[px]) * IMG_C);
                    const float4 v11 = *(const float4*)(base + (r1 + x1i[px]) * IMG_C);

                    bsum.x += w00 * v00.x + w01 * v01.x + w10 * v10.x + w11 * v11.x;
                    bsum.y += w00 * v00.y + w01 * v01.y + w10 * v10.y + w11 * v11.y;
                    bsum.z += w00 * v00.z + w01 * v01.z + w10 * v10.z + w11 * v11.z;
                    bsum.w += w00 * v00.w + w01 * v01.w + w10 * v10.w + w11 * v11.w;
                }
            }
            acc.x += wb * bsum.x;
            acc.y += wb * bsum.y;
            acc.z += wb * bsum.z;
            acc.w += wb * bsum.w;
        }
    }

    const float scale = 1.0f / (float)(TBINS * CROP * CROP);  // 1/81
    float4 o;
    o.x = acc.x * scale;
    o.y = acc.y * scale;
    o.z = acc.z * scale;
    o.w = acc.w * scale;
    *(float4*)(out + (size_t)box * CS + lane * 4) = o;
}

extern "C" void kernel_launch(void* const* d_in, const int* in_sizes, int n_in,
                              void* d_out, int out_size)
{
    const float* img   = (const float*)d_in[0];   // (B, 64, 64, 1152) f32
    const float* boxes = (const float*)d_in[1];   // (B, 512, 4) f32
    const float* wts   = (const float*)d_in[2];   // (1,1,1,1,9) f32
    float* out = (float*)d_out;                   // (B*512, 1, 1, 128) f32

    const int total_boxes     = in_sizes[1] / 4;
    const int B               = in_sizes[0] / (IMG_H * IMG_W * IMG_C);
    const int boxes_per_image = total_boxes / (B > 0 ? B : 1);

    const int blocks = (total_boxes + BOXES_PER_BLOCK - 1) / BOXES_PER_BLOCK;
    ps_pool_kernel<<<blocks, 32 * BOXES_PER_BLOCK>>>(
        img, boxes, wts, out, boxes_per_image, total_boxes);
}

// round 3
// speedup vs baseline: 1.7273x; 1.7273x over previous
#include <cuda_runtime.h>
#include <cuda_bf16.h>
#include <cstdint>

// PSAvgPooling: B=8, H=64, W=64, C=1152, N=512 boxes/image
// NUM_BINS=3 (TB=9), CROP=3, Cs = C/TB = 128.
//
// out[box, c] = (1/81) * sum_bin w[bin] * sum_{3x3 samples} bilinear(img[.,., bin*128+c])
//
// R3 layout: ONE BLOCK PER BOX, 9 warps = one warp per bin.
//  - each warp: 9 samples x 4 bilinear corners = 36 coalesced LDG.128
//    (lane owns 4 channels -> one 512B gather per corner)
//  - per-bin weighted sums land in smem, 128 threads reduce across the 9 bins.
// Rationale: R2 showed occ=25% (regs=77) with no pipe >35% -> latency bound.
// This gives 9x the warps and much lower register state per warp.

#define IMG_H 64
#define IMG_W 64
#define IMG_C 1152
#define CS    128           // channels per bin slice
#define NBINS 3
#define TBINS 9
#define CROP  3
#define THREADS (32 * TBINS)   // 288: one warp per bin

__global__ __launch_bounds__(THREADS, 4)
void ps_pool_kernel(const float* __restrict__ img,
                    const float* __restrict__ boxes,
                    const float* __restrict__ wts,
                    float* __restrict__ out,
                    int boxes_per_image,
                    int total_boxes)
{
    __shared__ float psum[TBINS][CS];

    const int box = blockIdx.x;
    if (box >= total_boxes) return;

    const int warp = threadIdx.x >> 5;   // = bin index 0..8
    const int lane = threadIdx.x & 31;

    const int b_img = box / boxes_per_image;
    const float* __restrict__ im =
        img + (size_t)b_img * (IMG_H * (size_t)IMG_W * IMG_C);

    // box coords (broadcast load — all lanes same address)
    const float y1 = __ldg(&boxes[box * 4 + 0]);
    const float x1 = __ldg(&boxes[box * 4 + 1]);
    const float y2 = __ldg(&boxes[box * 4 + 2]);
    const float x2 = __ldg(&boxes[box * 4 + 3]);
    const float sy = (y2 - y1) * (1.0f / NBINS);
    const float sx = (x2 - x1) * (1.0f / NBINS);

    const int by = warp / NBINS;         // bin row
    const int bx = warp - by * NBINS;    // bin col
    const int bin = warp;

    // 3 y-sample rows for this bin
    int   y0i[CROP], y1i[CROP];
    float wyv[CROP];
    bool  iny[CROP];
    #pragma unroll
    for (int py = 0; py < CROP; py++) {
        float yy = (y1 + ((float)by + 0.5f * (float)py) * sy) * (float)(IMG_H - 1);
        iny[py] = (yy >= 0.f) && (yy <= (float)(IMG_H - 1));
        float y0f = floorf(yy);
        wyv[py] = yy - y0f;
        int y0 = (int)y0f;
        y0 = min(max(y0, 0), IMG_H - 1);
        y0i[py] = y0;
        y1i[py] = min(y0 + 1, IMG_H - 1);
    }

    // 3 x-sample columns for this bin
    int   x0i[CROP], x1i[CROP];
    float wxv[CROP];
    bool  inx[CROP];
    #pragma unroll
    for (int px = 0; px < CROP; px++) {
        float xx = (x1 + ((float)bx + 0.5f * (float)px) * sx) * (float)(IMG_W - 1);
        inx[px] = (xx >= 0.f) && (xx <= (float)(IMG_W - 1));
        float x0f = floorf(xx);
        wxv[px] = xx - x0f;
        int x0 = (int)x0f;
        x0 = min(max(x0, 0), IMG_W - 1);
        x0i[px] = x0;
        x1i[px] = min(x0 + 1, IMG_W - 1);
    }

    const float* __restrict__ base = im + bin * CS + lane * 4;
    const float wb = __ldg(&wts[bin]);

    float4 bsum = make_float4(0.f, 0.f, 0.f, 0.f);

    #pragma unroll
    for (int py = 0; py < CROP; py++) {
        const float wy  = wyv[py];
        const size_t r0 = (size_t)y0i[py] * IMG_W;
        const size_t r1 = (size_t)y1i[py] * IMG_W;
        #pragma unroll
        for (int px = 0; px < CROP; px++) {
            const float wx = wxv[px];
            const float m  = (iny[py] && inx[px]) ? 1.0f : 0.0f;
            const float w00 = m * (1.f - wy) * (1.f - wx);
            const float w01 = m * (1.f - wy) * wx;
            const float w10 = m * wy * (1.f - wx);
            const float w11 = m * wy * wx;

            const float4 v00 = *(const float4*)(base + (r0 + x0i[px]) * IMG_C);
            const float4 v01 = *(const float4*)(base + (r0 + x1i[px]) * IMG_C);
            const float4 v10 = *(const float4*)(base + (r1 + x0i[px]) * IMG_C);
            const float4 v11 = *(const float4*)(base + (r1 + x1i[px]) * IMG_C);

            bsum.x += w00 * v00.x + w01 * v01.x + w10 * v10.x + w11 * v11.x;
            bsum.y += w00 * v00.y + w01 * v01.y + w10 * v10.y + w11 * v11.y;
            bsum.z += w00 * v00.z + w01 * v01.z + w10 * v10.z + w11 * v11.z;
            bsum.w += w00 * v00.w + w01 * v01.w + w10 * v10.w + w11 * v11.w;
        }
    }

    // weighted per-bin partial into smem
    float4* dst = (float4*)&psum[bin][lane * 4];
    dst->x = wb * bsum.x;
    dst->y = wb * bsum.y;
    dst->z = wb * bsum.z;
    dst->w = wb * bsum.w;

    __syncthreads();

    // reduce 9 bins -> 128 channels; first 128 threads, coalesced 512B store
    if (threadIdx.x < CS) {
        const int c = threadIdx.x;
        float s = 0.f;
        #pragma unroll
        for (int b = 0; b < TBINS; b++) s += psum[b][c];
        out[(size_t)box * CS + c] = s * (1.0f / (float)(TBINS * CROP * CROP));
    }
}

extern "C" void kernel_launch(void* const* d_in, const int* in_sizes, int n_in,
                              void* d_out, int out_size)
{
    const float* img   = (const float*)d_in[0];   // (B, 64, 64, 1152) f32
    const float* boxes = (const float*)d_in[1];   // (B, 512, 4) f32
    const float* wts   = (const float*)d_in[2];   // (1,1,1,1,9) f32
    float* out = (float*)d_out;                   // (B*512, 1, 1, 128) f32

    const int total_boxes     = in_sizes[1] / 4;
    const int B               = in_sizes[0] / (IMG_H * IMG_W * IMG_C);
    const int boxes_per_image = total_boxes / (B > 0 ? B : 1);

    ps_pool_kernel<<<total_boxes, THREADS>>>(
        img, boxes, wts, out, boxes_per_image, total_boxes);
}